// round 1
// baseline (speedup 1.0000x reference)
#include <cuda_runtime.h>
#include <cuda_bf16.h>

#define NN 50000
#define EE 600000
#define DIM 128
#define NB ((NN + 1023) / 1024)   // 49 scan blocks
#define TOT (EE + NN)             // 650000 CSR entries (edges + self-loops)

// ---------------- scratch (static device globals; no allocation) ----------------
__device__ int   g_deg[NN];
__device__ float g_dinv[NN];
__device__ int   g_rowptr[NN + 1];
__device__ int   g_pos[NN];
__device__ int   g_col[TOT];
__device__ float g_w[TOT];
__device__ int   g_bsum[NB + 1];
__device__ float g_h[(size_t)NN * DIM];   // GEMM output scratch
__device__ float g_z[(size_t)NN * DIM];   // layer-1 activation scratch

// ---------------- degree / norm ----------------
__global__ void k_init_deg() {
    int i = blockIdx.x * blockDim.x + threadIdx.x;
    if (i < NN) g_deg[i] = 1;   // self-loop
}

__global__ void k_count_deg(const int* __restrict__ dst) {
    int e = blockIdx.x * blockDim.x + threadIdx.x;
    if (e < EE) atomicAdd(&g_deg[dst[e]], 1);
}

__global__ void k_dinv() {
    int i = blockIdx.x * blockDim.x + threadIdx.x;
    if (i < NN) g_dinv[i] = rsqrtf((float)g_deg[i]);
}

// ---------------- exclusive scan of g_deg -> g_rowptr ----------------
__global__ void k_scan1() {
    __shared__ int s[1024];
    int t = threadIdx.x;
    int i = blockIdx.x * 1024 + t;
    int v = (i < NN) ? g_deg[i] : 0;
    s[t] = v;
    __syncthreads();
#pragma unroll
    for (int off = 1; off < 1024; off <<= 1) {
        int x = (t >= off) ? s[t - off] : 0;
        __syncthreads();
        s[t] += x;
        __syncthreads();
    }
    if (i < NN) g_rowptr[i] = s[t] - v;              // exclusive within block
    if (t == 1023) g_bsum[blockIdx.x] = s[1023];     // block total
}

__global__ void k_scan2() {
    if (threadIdx.x == 0 && blockIdx.x == 0) {
        int run = 0;
        for (int b = 0; b < NB; b++) {
            int x = g_bsum[b];
            g_bsum[b] = run;
            run += x;
        }
        g_bsum[NB] = run;
    }
}

__global__ void k_scan3() {
    int t = threadIdx.x;
    int i = blockIdx.x * 1024 + t;
    if (i < NN) {
        int r = g_rowptr[i] + g_bsum[blockIdx.x];
        g_rowptr[i] = r;
        g_pos[i] = r;
    }
    if (i == 0) g_rowptr[NN] = TOT;
}

// ---------------- CSR fill (edges + self-loops) ----------------
__global__ void k_scatter(const int* __restrict__ src, const int* __restrict__ dst) {
    int e = blockIdx.x * blockDim.x + threadIdx.x;
    if (e >= TOT) return;
    int s, d;
    if (e < EE) { s = src[e]; d = dst[e]; }
    else        { s = d = e - EE; }
    int p = atomicAdd(&g_pos[d], 1);
    g_col[p] = s;
    g_w[p]   = g_dinv[s] * g_dinv[d];
}

// ---------------- GEMM: C[M,128] = A[M,128] @ B[128,128] ----------------
// BM=64, BN=128, BK=8, 256 threads, 8x4 microtile per thread.
__global__ void __launch_bounds__(256) k_gemm128(const float* __restrict__ A,
                                                 const float* __restrict__ B,
                                                 float* __restrict__ C, int M) {
    __shared__ float As[8][64];
    __shared__ float Bs[8][128];
    int tid = threadIdx.x;
    int m0 = blockIdx.x * 64;

    int ar = tid >> 2;          // 0..63  (A row within tile)
    int ak = (tid & 3) * 2;     // 0,2,4,6 (A k within tile, float2)
    int br = tid >> 5;          // 0..7   (B k row)
    int bc = (tid & 31) * 4;    // 0..124 (B col, float4)
    int tm = (tid >> 5) * 8;    // thread microtile row base
    int tn = (tid & 31) * 4;    // thread microtile col base

    float acc[8][4];
#pragma unroll
    for (int i = 0; i < 8; i++)
#pragma unroll
        for (int j = 0; j < 4; j++) acc[i][j] = 0.f;

    for (int k0 = 0; k0 < 128; k0 += 8) {
        int row = m0 + ar;
        float2 av = make_float2(0.f, 0.f);
        if (row < M) av = *(const float2*)&A[(size_t)row * 128 + k0 + ak];
        As[ak][ar]     = av.x;
        As[ak + 1][ar] = av.y;
        float4 bv = *(const float4*)&B[(size_t)(k0 + br) * 128 + bc];
        *(float4*)&Bs[br][bc] = bv;
        __syncthreads();
#pragma unroll
        for (int k = 0; k < 8; k++) {
            float a[8], b[4];
            *(float4*)&a[0] = *(float4*)&As[k][tm];
            *(float4*)&a[4] = *(float4*)&As[k][tm + 4];
            *(float4*)&b[0] = *(float4*)&Bs[k][tn];
#pragma unroll
            for (int i = 0; i < 8; i++)
#pragma unroll
                for (int j = 0; j < 4; j++) acc[i][j] += a[i] * b[j];
        }
        __syncthreads();
    }
#pragma unroll
    for (int i = 0; i < 8; i++) {
        int row = m0 + tm + i;
        if (row < M) *(float4*)&C[(size_t)row * 128 + tn] = *(float4*)&acc[i][0];
    }
}

// ---------------- aggregation: out[n] = relu(sum_e w[e]*h[col[e]] + bias) ----------------
// one warp per node; atomic-free scatter via CSR.
__global__ void __launch_bounds__(256) k_aggregate(const float* __restrict__ h,
                                                   const float* __restrict__ bias,
                                                   float* __restrict__ out) {
    int warp = (blockIdx.x * blockDim.x + threadIdx.x) >> 5;
    int lane = threadIdx.x & 31;
    if (warp >= NN) return;
    int beg = g_rowptr[warp];
    int end = g_rowptr[warp + 1];

    float ax = 0.f, ay = 0.f, az = 0.f, aw = 0.f;
    int e = beg;
    for (; e + 1 < end; e += 2) {
        int   c0 = g_col[e],   c1 = g_col[e + 1];
        float w0 = g_w[e],     w1 = g_w[e + 1];
        float4 v0 = *(const float4*)&h[(size_t)c0 * 128 + lane * 4];
        float4 v1 = *(const float4*)&h[(size_t)c1 * 128 + lane * 4];
        ax += w0 * v0.x + w1 * v1.x;
        ay += w0 * v0.y + w1 * v1.y;
        az += w0 * v0.z + w1 * v1.z;
        aw += w0 * v0.w + w1 * v1.w;
    }
    if (e < end) {
        int c = g_col[e];
        float w0 = g_w[e];
        float4 v = *(const float4*)&h[(size_t)c * 128 + lane * 4];
        ax += w0 * v.x; ay += w0 * v.y; az += w0 * v.z; aw += w0 * v.w;
    }
    float4 bv = *(const float4*)&bias[lane * 4];
    float4 o;
    o.x = fmaxf(ax + bv.x, 0.f);
    o.y = fmaxf(ay + bv.y, 0.f);
    o.z = fmaxf(az + bv.z, 0.f);
    o.w = fmaxf(aw + bv.w, 0.f);
    *(float4*)&out[(size_t)warp * 128 + lane * 4] = o;
}

// ---------------- launch ----------------
extern "C" void kernel_launch(void* const* d_in, const int* in_sizes, int n_in,
                              void* d_out, int out_size) {
    const float* x   = (const float*)d_in[0];
    const int*   ei  = (const int*)d_in[1];       // [2, E]: row0 src, row1 dst
    const float* W1  = (const float*)d_in[2];
    const float* b1  = (const float*)d_in[3];
    const float* W2  = (const float*)d_in[4];
    const float* b2  = (const float*)d_in[5];
    float* out = (float*)d_out;

    const int* src = ei;
    const int* dst = ei + EE;

    // --- GCN normalization + CSR build ---
    k_init_deg<<<(NN + 255) / 256, 256>>>();
    k_count_deg<<<(EE + 255) / 256, 256>>>(dst);
    k_dinv<<<(NN + 255) / 256, 256>>>();
    k_scan1<<<NB, 1024>>>();
    k_scan2<<<1, 32>>>();
    k_scan3<<<NB, 1024>>>();
    k_scatter<<<(TOT + 255) / 256, 256>>>(src, dst);

    const int gemm_blocks = (NN + 63) / 64;
    const int agg_blocks  = (NN * 32 + 255) / 256;

    // --- layer 1 ---
    k_gemm128<<<gemm_blocks, 256>>>(x, W1, g_h, NN);
    k_aggregate<<<agg_blocks, 256>>>(g_h, b1, g_z);
    // --- layer 2 ---
    k_gemm128<<<gemm_blocks, 256>>>(g_z, W2, g_h, NN);
    k_aggregate<<<agg_blocks, 256>>>(g_h, b2, out);
}